// round 1
// baseline (speedup 1.0000x reference)
#include <cuda_runtime.h>
#include <cuda_bf16.h>
#include <math.h>

// FNO spectral layer, B=16, H=W=128, C_in=C_out=64, MODES=16.
// Decomposed into 5 partial-DFT / contraction stages. Only the low 16x16
// frequency corner is ever computed (the reference's full rfft2/irfft2 is
// mathematically equivalent to these truncated DFTs for this layer).

#define B   16
#define Hh  128
#define Ww  128
#define CI  64
#define CO  64
#define MD  16

// Scratch (device globals: allocation-free rule)
static __device__ float2 g_A[B * MD * Hh * CI];       // [b][kx][h][i]   16 MB
static __device__ float2 g_X[MD * MD * B * CI];       // [ky][kx][b][i]   2 MB
static __device__ float2 g_O[B * MD * MD * CO];       // [b][kx][ky][o]   2 MB
static __device__ float2 g_G[B * Hh * MD * CO];       // [b][h][kx][o]   16 MB

#define TWO_PI_OVER_128 0.04908738521234052f  // 2*pi/128

__device__ __forceinline__ void fill_twiddle(float2* tw, int tid) {
    if (tid < 128) {
        float s, c;
        sincosf((float)tid * TWO_PI_OVER_128, &s, &c);
        tw[tid] = make_float2(c, s);
    }
}

// Stage A: A[b][kx][h][i] = sum_w x[b][h][w][i] * e^{-2pi i * kx*w/128}
__global__ void stageA(const float* __restrict__ x) {
    __shared__ float  sx[Ww * CI];   // 32 KB
    __shared__ float2 tw[128];
    int b = blockIdx.x >> 7;
    int h = blockIdx.x & 127;
    int tid = threadIdx.x;          // 256 threads
    fill_twiddle(tw, tid);
    const float* xrow = x + ((size_t)(b * Hh + h)) * Ww * CI;
    for (int l = tid; l < Ww * CI; l += 256) sx[l] = xrow[l];
    __syncthreads();

    int i  = tid & 63;
    int kq = tid >> 6;              // kx = kq + 4*q
    float aR[4] = {0.f, 0.f, 0.f, 0.f};
    float aI[4] = {0.f, 0.f, 0.f, 0.f};
    for (int w = 0; w < Ww; ++w) {
        float v = sx[w * CI + i];
#pragma unroll
        for (int q = 0; q < 4; ++q) {
            int kx = kq + 4 * q;
            float2 t = tw[(kx * w) & 127];
            aR[q] += v * t.x;
            aI[q] -= v * t.y;
        }
    }
#pragma unroll
    for (int q = 0; q < 4; ++q) {
        int kx = kq + 4 * q;
        g_A[((b * MD + kx) * Hh + h) * CI + i] = make_float2(aR[q], aI[q]);
    }
}

// Stage B: X[ky][kx][b][i] = sum_h A[b][kx][h][i] * e^{-2pi i * ky*h/128}
__global__ void stageB() {
    __shared__ float2 sA[Hh * 32];  // 32 KB (i-chunk of 32)
    __shared__ float2 tw[128];
    int b  = blockIdx.x >> 4;
    int kx = blockIdx.x & 15;
    int tid = threadIdx.x;          // 256
    fill_twiddle(tw, tid);
    const float2* Ab = &g_A[(b * MD + kx) * Hh * CI];

    for (int chunk = 0; chunk < 2; ++chunk) {
        int ib = chunk * 32;
        __syncthreads();
        for (int l = tid; l < Hh * 32; l += 256) {
            int h = l >> 5, ii = l & 31;
            sA[l] = Ab[h * CI + ib + ii];
        }
        __syncthreads();
        int ii = tid & 31;
        int kg = tid >> 5;          // ky = kg and kg+8
        float r0 = 0.f, m0 = 0.f, r1 = 0.f, m1 = 0.f;
        for (int h = 0; h < Hh; ++h) {
            float2 a  = sA[h * 32 + ii];
            float2 t0 = tw[(kg * h) & 127];
            float2 t1 = tw[((kg + 8) * h) & 127];
            // a * e^{-i th} = (ar*c + ai*s) + i(ai*c - ar*s)
            r0 += a.x * t0.x + a.y * t0.y;
            m0 += a.y * t0.x - a.x * t0.y;
            r1 += a.x * t1.x + a.y * t1.y;
            m1 += a.y * t1.x - a.x * t1.y;
        }
        int i = ib + ii;
        g_X[((kg       * MD + kx) * B + b) * CI + i] = make_float2(r0, m0);
        g_X[(((kg + 8) * MD + kx) * B + b) * CI + i] = make_float2(r1, m1);
    }
}

// Stage C: O[b][kx][ky][o] = sum_i X[ky][kx][b][i] * (Wr + j Wi)[i][o][ky][kx]
__global__ void stageC(const float* __restrict__ wr, const float* __restrict__ wi) {
    __shared__ float  sWr[CI * CO];   // 16 KB
    __shared__ float  sWi[CI * CO];   // 16 KB
    __shared__ float2 sX[B * CI];     // 8 KB
    int ky = blockIdx.x >> 4;
    int kx = blockIdx.x & 15;
    int m  = ky * MD + kx;
    int tid = threadIdx.x;            // 256
    for (int l = tid; l < CI * CO; l += 256) {
        sWr[l] = wr[(size_t)l * 256 + m];
        sWi[l] = wi[(size_t)l * 256 + m];
    }
    const float2* Xb = &g_X[(ky * MD + kx) * B * CI];
    for (int l = tid; l < B * CI; l += 256) sX[l] = Xb[l];
    __syncthreads();

    int o  = tid & 63;
    int bg = tid >> 6;                // b = bg*4 + j
    float aR[4] = {0.f, 0.f, 0.f, 0.f};
    float aI[4] = {0.f, 0.f, 0.f, 0.f};
    for (int i = 0; i < CI; ++i) {
        float wrv = sWr[i * CO + o];
        float wiv = sWi[i * CO + o];
#pragma unroll
        for (int j = 0; j < 4; ++j) {
            float2 xv = sX[(bg * 4 + j) * CI + i];
            aR[j] += xv.x * wrv - xv.y * wiv;
            aI[j] += xv.x * wiv + xv.y * wrv;
        }
    }
#pragma unroll
    for (int j = 0; j < 4; ++j) {
        int b = bg * 4 + j;
        g_O[((b * MD + kx) * MD + ky) * CO + o] = make_float2(aR[j], aI[j]);
    }
}

// Stage D: G[b][h][kx][o] = sum_ky O[b][kx][ky][o] * e^{+2pi i * ky*h/128}
__global__ void stageD() {
    __shared__ float2 sO[MD * CO];    // 8 KB
    __shared__ float2 tw[128];
    int b  = blockIdx.x >> 4;
    int kx = blockIdx.x & 15;
    int tid = threadIdx.x;            // 256
    fill_twiddle(tw, tid);
    const float2* Ob = &g_O[(b * MD + kx) * MD * CO];
    for (int l = tid; l < MD * CO; l += 256) sO[l] = Ob[l];
    __syncthreads();

    int o  = tid & 63;
    int hg = tid >> 6;
    for (int j = 0; j < 32; ++j) {
        int h = hg * 32 + j;
        float r = 0.f, im = 0.f;
#pragma unroll
        for (int ky = 0; ky < MD; ++ky) {
            float2 v = sO[ky * CO + o];
            float2 t = tw[(ky * h) & 127];
            r  += v.x * t.x - v.y * t.y;
            im += v.x * t.y + v.y * t.x;
        }
        g_G[((b * Hh + h) * MD + kx) * CO + o] = make_float2(r, im);
    }
}

// Stage E: y[b][h][w][o] = scale * [ Re(G[kx=0]) + 2*sum_{kx=1..15} Re(G e^{+i th}) ]
__global__ void stageE(float* __restrict__ y) {
    __shared__ float2 sG[MD * CO];    // 8 KB
    __shared__ float2 tw[128];
    int b = blockIdx.x >> 7;
    int h = blockIdx.x & 127;
    int tid = threadIdx.x;            // 256
    fill_twiddle(tw, tid);
    const float2* Gb = &g_G[(b * Hh + h) * MD * CO];
    for (int l = tid; l < MD * CO; l += 256) sG[l] = Gb[l];
    __syncthreads();

    float* yrow = y + ((size_t)(b * Hh + h)) * Ww * CO;
    int o  = tid & 63;
    int wg = tid >> 6;
    const float scale = 1.0f / 16384.0f;   // ortho fwd * ortho inv = 1/(H*W)
    for (int j = 0; j < 32; ++j) {
        int w = wg * 32 + j;
        float acc = sG[o].x;               // kx = 0 term (Im dropped by c2r)
#pragma unroll
        for (int kx = 1; kx < MD; ++kx) {
            float2 v = sG[kx * CO + o];
            float2 t = tw[(kx * w) & 127];
            acc += 2.0f * (v.x * t.x - v.y * t.y);
        }
        yrow[w * CO + o] = acc * scale;
    }
}

extern "C" void kernel_launch(void* const* d_in, const int* in_sizes, int n_in,
                              void* d_out, int out_size) {
    const float* x  = (const float*)d_in[0];
    const float* wr = (const float*)d_in[1];
    const float* wi = (const float*)d_in[2];
    float* y = (float*)d_out;

    stageA<<<B * Hh, 256>>>(x);
    stageB<<<B * MD, 256>>>();
    stageC<<<MD * MD, 256>>>(wr, wi);
    stageD<<<B * MD, 256>>>();
    stageE<<<B * Hh, 256>>>(y);
}

// round 3
// speedup vs baseline: 1.1970x; 1.1970x over previous
#include <cuda_runtime.h>
#include <math.h>

#define B   16
#define Hh  128
#define Ww  128
#define CI  64
#define CO  64
#define MD  16
#define THETA 0.04908738521234052f   // 2*pi/128

typedef unsigned long long u64;

// ---- packed f32x2 helpers (Blackwell FFMA2) ----
__device__ __forceinline__ u64 pk(float lo, float hi) {
    u64 r; asm("mov.b64 %0, {%1,%2};" : "=l"(r) : "f"(lo), "f"(hi)); return r;
}
__device__ __forceinline__ void upk(u64 v, float& lo, float& hi) {
    asm("mov.b64 {%0,%1}, %2;" : "=f"(lo), "=f"(hi) : "l"(v));
}
__device__ __forceinline__ u64 fma2(u64 a, u64 b, u64 c) {
    u64 d; asm("fma.rn.f32x2 %0, %1, %2, %3;" : "=l"(d) : "l"(a), "l"(b), "l"(c)); return d;
}

// ---- scratch (device globals; allocation-free rule). 16B-aligned for vector LDG/STG ----
static __device__ __align__(16) float2 g_A [B*MD*Hh*CI];     // [b][kx][h][i]   16 MB
static __device__ __align__(16) float2 g_X [MD*MD*B*CI];     // [m][b][i]        2 MB
static __device__ __align__(16) float2 g_W2[MD*MD*CI*CO];    // [m][i*64+o]      8 MB
static __device__ __align__(16) float2 g_O [B*MD*MD*CO];     // [b][kx][ky][o]   2 MB
static __device__ __align__(16) float  g_Gx[B*Hh*MD*CO];     // [b][h][kx][o]    8 MB
static __device__ __align__(16) float  g_Gy[B*Hh*MD*CO];     //                  8 MB

// ============ stage T: weight transpose to [m][i*64+o] (coalesced) ============
__global__ void __launch_bounds__(256) stageT(const float* __restrict__ wr,
                                              const float* __restrict__ wi) {
    __shared__ float sr[32][33];
    __shared__ float si[32][33];
    int bm  = blockIdx.x & 7;     // m-tile (8 x 32)
    int bio = blockIdx.x >> 3;    // io-tile (128 x 32)
    int tx  = threadIdx.x & 31;
    int ty  = threadIdx.x >> 5;   // 0..7
#pragma unroll
    for (int r = 0; r < 4; ++r) {
        int iol = ty + r * 8;
        size_t g = (size_t)(bio * 32 + iol) * 256 + bm * 32 + tx;
        sr[iol][tx] = wr[g];
        si[iol][tx] = wi[g];
    }
    __syncthreads();
#pragma unroll
    for (int r = 0; r < 4; ++r) {
        int ml = ty + r * 8;
        g_W2[(size_t)(bm * 32 + ml) * 4096 + bio * 32 + tx] =
            make_float2(sr[tx][ml], si[tx][ml]);
    }
}

// ============ stage A: A[b][kx][h][i] = sum_w x[b,h,w,i] e^{-i kx w th} ============
__global__ void __launch_bounds__(128) stageA(const float* __restrict__ x) {
    __shared__ __align__(16) float  sx [Ww * CI];   // 32 KB
    __shared__ __align__(16) float2 twk[MD * 128];  // 16 KB  (c, -s) per [kx][w]
    int b = blockIdx.x >> 7, h = blockIdx.x & 127;
    int tid = threadIdx.x;

    for (int l = tid; l < MD * 128; l += 128) {
        int kx = l >> 7, w = l & 127;
        float s, c;
        sincosf((float)((kx * w) & 127) * THETA, &s, &c);
        twk[l] = make_float2(c, -s);
    }
    const float4* xr = (const float4*)(x + (size_t)(b * Hh + h) * Ww * CI);
    float4* sx4 = (float4*)sx;
    for (int l = tid; l < Ww * CI / 4; l += 128) sx4[l] = xr[l];
    __syncthreads();

    int ii = tid & 31;
    int kq = tid >> 5;                       // kx = kq + 4q
    const u64* t0 = (const u64*)&twk[(kq     ) * 128];
    const u64* t1 = (const u64*)&twk[(kq +  4) * 128];
    const u64* t2 = (const u64*)&twk[(kq +  8) * 128];
    const u64* t3 = (const u64*)&twk[(kq + 12) * 128];
    u64 a00=0,a01=0,a10=0,a11=0,a20=0,a21=0,a30=0,a31=0;
#pragma unroll 8
    for (int w = 0; w < Ww; ++w) {
        float v0 = sx[w * 64 + ii], v1 = sx[w * 64 + ii + 32];
        u64 p0 = pk(v0, v0), p1 = pk(v1, v1);
        a00 = fma2(p0, t0[w], a00);  a01 = fma2(p1, t0[w], a01);
        a10 = fma2(p0, t1[w], a10);  a11 = fma2(p1, t1[w], a11);
        a20 = fma2(p0, t2[w], a20);  a21 = fma2(p1, t2[w], a21);
        a30 = fma2(p0, t3[w], a30);  a31 = fma2(p1, t3[w], a31);
    }
    size_t base;
    base = ((size_t)(b * MD + kq     ) * Hh + h) * CI;
    *(u64*)&g_A[base + ii] = a00;  *(u64*)&g_A[base + ii + 32] = a01;
    base = ((size_t)(b * MD + kq +  4) * Hh + h) * CI;
    *(u64*)&g_A[base + ii] = a10;  *(u64*)&g_A[base + ii + 32] = a11;
    base = ((size_t)(b * MD + kq +  8) * Hh + h) * CI;
    *(u64*)&g_A[base + ii] = a20;  *(u64*)&g_A[base + ii + 32] = a21;
    base = ((size_t)(b * MD + kq + 12) * Hh + h) * CI;
    *(u64*)&g_A[base + ii] = a30;  *(u64*)&g_A[base + ii + 32] = a31;
}

// ============ stage B: X[m=(ky,kx)][b][i] = sum_h A[b,kx,h,i] e^{-i ky h th} ============
__global__ void __launch_bounds__(256) stageB() {
    __shared__ __align__(16) float2 tcc[MD * 128];  // (c,c)  16 KB
    __shared__ __align__(16) float2 tss[MD * 128];  // (s,s)  16 KB
    int b = blockIdx.x >> 4, kx = blockIdx.x & 15;
    int tid = threadIdx.x;
    for (int l = tid; l < MD * 128; l += 256) {
        int ky = l >> 7, h = l & 127;
        float s, c;
        sincosf((float)((ky * h) & 127) * THETA, &s, &c);
        tcc[l] = make_float2(c, c);
        tss[l] = make_float2(s, s);
    }
    __syncthreads();

    int ii = tid & 15;       // i = ii + 16t
    int ky = tid >> 4;
    const u64* pc = (const u64*)&tcc[ky * 128];
    const u64* ps = (const u64*)&tss[ky * 128];
    const u64* Ab = (const u64*)&g_A[(size_t)(b * MD + kx) * Hh * CI];
    u64 c0=0, c1=0, c2=0, c3=0;
#pragma unroll 4
    for (int h = 0; h < Hh; ++h) {
        u64 cc = pc[h], ss = ps[h];
        u64 a0 = Ab[h * 64 + ii];
        u64 a1 = Ab[h * 64 + ii + 16];
        u64 a2 = Ab[h * 64 + ii + 32];
        u64 a3 = Ab[h * 64 + ii + 48];
        float x0,y0,x1,y1,x2,y2,x3,y3;
        upk(a0,x0,y0); upk(a1,x1,y1); upk(a2,x2,y2); upk(a3,x3,y3);
        // (re,im) += (ax*c + ay*s, ay*c - ax*s) = a*(c,c) + (ay,-ax)*(s,s)
        c0 = fma2(a0, cc, c0);  c0 = fma2(pk(y0, -x0), ss, c0);
        c1 = fma2(a1, cc, c1);  c1 = fma2(pk(y1, -x1), ss, c1);
        c2 = fma2(a2, cc, c2);  c2 = fma2(pk(y2, -x2), ss, c2);
        c3 = fma2(a3, cc, c3);  c3 = fma2(pk(y3, -x3), ss, c3);
    }
    size_t base = ((size_t)(ky * MD + kx) * B + b) * CI;
    *(u64*)&g_X[base + ii     ] = c0;
    *(u64*)&g_X[base + ii + 16] = c1;
    *(u64*)&g_X[base + ii + 32] = c2;
    *(u64*)&g_X[base + ii + 48] = c3;
}

// ============ stage C: O[b][kx][ky][o] = sum_i X[m][b][i] * W[m][i][o] (complex) ============
__global__ void __launch_bounds__(256) stageC() {
    __shared__ __align__(16) float2 sW [CI * CO];   // 32 KB
    __shared__ __align__(16) u64    sXx[B * CI];    // 8 KB  (x.x, x.x)
    __shared__ __align__(16) u64    sXy[B * CI];    // 8 KB  (x.y, x.y)
    int m = blockIdx.x;
    int kxm = m & 15, kym = m >> 4;
    int tid = threadIdx.x;
    const float4* Wsrc = (const float4*)&g_W2[(size_t)m * CI * CO];
    float4* sW4 = (float4*)sW;
    for (int l = tid; l < CI * CO / 2; l += 256) sW4[l] = Wsrc[l];
    const float2* Xs = &g_X[(size_t)m * B * CI];
    for (int l = tid; l < B * CI; l += 256) {
        float2 v = Xs[l];
        sXx[l] = pk(v.x, v.x);
        sXy[l] = pk(v.y, v.y);
    }
    __syncthreads();

    int o = tid & 63, bg = tid >> 6;   // b = bg*4 + j
    u64 acc0=0, acc1=0, acc2=0, acc3=0;
    const u64* x0 = &sXx[(bg*4+0)*64]; const u64* y0 = &sXy[(bg*4+0)*64];
    const u64* x1 = &sXx[(bg*4+1)*64]; const u64* y1 = &sXy[(bg*4+1)*64];
    const u64* x2 = &sXx[(bg*4+2)*64]; const u64* y2 = &sXy[(bg*4+2)*64];
    const u64* x3 = &sXx[(bg*4+3)*64]; const u64* y3 = &sXy[(bg*4+3)*64];
#pragma unroll 4
    for (int i = 0; i < CI; ++i) {
        u64 w1 = *(const u64*)&sW[i * 64 + o];   // (wx, wy)
        float wx, wy; upk(w1, wx, wy);
        u64 w2 = pk(-wy, wx);
        acc0 = fma2(x0[i], w1, acc0);  acc0 = fma2(y0[i], w2, acc0);
        acc1 = fma2(x1[i], w1, acc1);  acc1 = fma2(y1[i], w2, acc1);
        acc2 = fma2(x2[i], w1, acc2);  acc2 = fma2(y2[i], w2, acc2);
        acc3 = fma2(x3[i], w1, acc3);  acc3 = fma2(y3[i], w2, acc3);
    }
    *(u64*)&g_O[((size_t)((bg*4+0) * MD + kxm) * MD + kym) * CO + o] = acc0;
    *(u64*)&g_O[((size_t)((bg*4+1) * MD + kxm) * MD + kym) * CO + o] = acc1;
    *(u64*)&g_O[((size_t)((bg*4+2) * MD + kxm) * MD + kym) * CO + o] = acc2;
    *(u64*)&g_O[((size_t)((bg*4+3) * MD + kxm) * MD + kym) * CO + o] = acc3;
}

// ============ stage D: G[b][h][kx][o] = sum_ky O[b,kx,ky,o] e^{+i ky h th} (SoA out) ============
__global__ void __launch_bounds__(256) stageD() {
    __shared__ __align__(16) float  sOx[MD * CO];   // 4 KB
    __shared__ __align__(16) float  sOy[MD * CO];   // 4 KB
    __shared__ __align__(16) float2 tcc[MD * 64];   // (c,c) 8 KB   [ky][hloc]
    __shared__ __align__(16) float2 tsp[MD * 64];   // (s,s) 8 KB
    int half = blockIdx.x & 1;
    int kx   = (blockIdx.x >> 1) & 15;
    int b    = blockIdx.x >> 5;
    int hb   = half * 64;
    int tid  = threadIdx.x;
    for (int l = tid; l < MD * 64; l += 256) {
        int ky = l >> 6, hloc = l & 63;
        float s, c;
        sincosf((float)((ky * (hb + hloc)) & 127) * THETA, &s, &c);
        tcc[l] = make_float2(c, c);
        tsp[l] = make_float2(s, s);
    }
    const float2* Os = &g_O[(size_t)(b * MD + kx) * MD * CO];
    for (int l = tid; l < MD * CO; l += 256) { float2 v = Os[l]; sOx[l] = v.x; sOy[l] = v.y; }
    __syncthreads();

    int op = tid & 31;     // o = 2*op
    int hl = tid >> 5;     // hloc = hl*8 + jj
    const u64 SGN = 0x8000000080000000ULL;
    u64 re[8] = {0,0,0,0,0,0,0,0};
    u64 im[8] = {0,0,0,0,0,0,0,0};
#pragma unroll
    for (int ky = 0; ky < MD; ++ky) {
        u64 vx  = *(const u64*)&sOx[ky * 64 + op * 2];
        u64 vy  = *(const u64*)&sOy[ky * 64 + op * 2];
        u64 vyn = vy ^ SGN;
#pragma unroll
        for (int jj = 0; jj < 8; ++jj) {
            int hloc = hl * 8 + jj;
            u64 cc = *(const u64*)&tcc[ky * 64 + hloc];
            u64 ss = *(const u64*)&tsp[ky * 64 + hloc];
            re[jj] = fma2(vx,  cc, re[jj]);  re[jj] = fma2(vyn, ss, re[jj]);
            im[jj] = fma2(vx,  ss, im[jj]);  im[jj] = fma2(vy,  cc, im[jj]);
        }
    }
#pragma unroll
    for (int jj = 0; jj < 8; ++jj) {
        int h = hb + hl * 8 + jj;
        size_t base = ((size_t)(b * Hh + h) * MD + kx) * CO + op * 2;
        *(u64*)&g_Gx[base] = re[jj];
        *(u64*)&g_Gy[base] = im[jj];
    }
}

// ============ stage E: y[b,h,w,o] = S*[Gx(0,o) + sum_{kx>=1} 2(Gx c - Gy s)] ============
#define YPAD 66   // even padding: keeps u64 alignment of sY rows
__global__ void __launch_bounds__(128) stageE(float* __restrict__ y) {
    __shared__ __align__(16) float sGx[MD * CO];    // 4 KB
    __shared__ __align__(16) float sGy[MD * CO];    // 4 KB
    __shared__ __align__(16) float sY [Ww * YPAD];  // 33.8 KB
    int b = blockIdx.x >> 7, h = blockIdx.x & 127;
    int tid = threadIdx.x;                           // = w
    const float4* Gxs = (const float4*)&g_Gx[(size_t)(b * Hh + h) * MD * CO];
    const float4* Gys = (const float4*)&g_Gy[(size_t)(b * Hh + h) * MD * CO];
    for (int l = tid; l < MD * CO / 4; l += 128) {
        ((float4*)sGx)[l] = Gxs[l];
        ((float4*)sGy)[l] = Gys[l];
    }
    const float S = 1.0f / 16384.0f;                 // ortho fwd*inv = 1/(H*W)
    u64 tc[16], ts[16];
    int w = tid;
    tc[0] = pk(S, S);  ts[0] = 0;
#pragma unroll
    for (int kx = 1; kx < MD; ++kx) {
        float s, c;
        sincosf((float)((kx * w) & 127) * THETA, &s, &c);
        float fc = 2.0f * S * c, fs = -2.0f * S * s;
        tc[kx] = pk(fc, fc);  ts[kx] = pk(fs, fs);
    }
    __syncthreads();

#pragma unroll 2
    for (int oq = 0; oq < 16; ++oq) {
        u64 a01 = 0, a23 = 0;
#pragma unroll
        for (int kx = 0; kx < MD; ++kx) {
            ulonglong2 vx = *(const ulonglong2*)&sGx[kx * 64 + oq * 4];
            ulonglong2 vy = *(const ulonglong2*)&sGy[kx * 64 + oq * 4];
            a01 = fma2(vx.x, tc[kx], a01);  a01 = fma2(vy.x, ts[kx], a01);
            a23 = fma2(vx.y, tc[kx], a23);  a23 = fma2(vy.y, ts[kx], a23);
        }
        *(u64*)&sY[w * YPAD + oq * 4    ] = a01;
        *(u64*)&sY[w * YPAD + oq * 4 + 2] = a23;
    }
    __syncthreads();
    float* yb = y + (size_t)(b * Hh + h) * Ww * CO;
    for (int l = tid; l < Ww * CO / 2; l += 128) {
        int idx = l * 2;
        int ww = idx >> 6, o = idx & 63;
        *(u64*)&yb[idx] = *(const u64*)&sY[ww * YPAD + o];
    }
}

extern "C" void kernel_launch(void* const* d_in, const int* in_sizes, int n_in,
                              void* d_out, int out_size) {
    const float* x  = (const float*)d_in[0];
    const float* wr = (const float*)d_in[1];
    const float* wi = (const float*)d_in[2];
    float* y = (float*)d_out;

    stageT<<<1024, 256>>>(wr, wi);
    stageA<<<B * Hh, 128>>>(x);
    stageB<<<B * MD, 256>>>();
    stageC<<<MD * MD, 256>>>();
    stageD<<<B * MD * 2, 256>>>();
    stageE<<<B * Hh, 128>>>(y);
}